// round 5
// baseline (speedup 1.0000x reference)
#include <cuda_runtime.h>
#include <cuda_bf16.h>

// y = D @ x per row, D = blockdiag(1024 x [4x4]) + diag(rem[3]).
// x: (ROWS, 4099) fp32. Row stride 4099 ≡ 3 (mod 4) -> groups are 16B-aligned
// only when r = (3*row)%4 == 0. This kernel does ALL global traffic as
// 128-bit aligned LDG/STG and fixes the group misalignment with warp shuffles:
//   load : lane loads aligned float4; shfl_down(1) supplies spill-over; lane31
//          patches 3 scalars from the next 16B.
//   store: shfl_up(1) reassembles aligned output quads; lane0/lane31 write the
//          <=3 boundary elements scalar.
// Cuts L1tex wavefronts ~3.5x vs scalar strided accesses (the R4 bottleneck).

#define BS  4
#define GPC 256   // groups (4x4 blocks) per CTA == blockDim.x
#define RPC 8     // rows per CTA

__global__ void __launch_bounds__(256) block_apply_vec_kernel(
    const float* __restrict__ x,
    const float* __restrict__ blocks,
    const float* __restrict__ dr,
    float* __restrict__ y,
    int n_blocks, int rem, int row_len, int total_rows)
{
    const int tid  = threadIdx.x;
    const int lane = tid & 31;
    const int g    = blockIdx.x * GPC + tid;          // this thread's block idx

    // 4x4 weights in registers (64B aligned -> 4x LDG.128, L1/L2 resident)
    const float4* bp = reinterpret_cast<const float4*>(blocks) + g * BS;
    const float4 w0 = __ldg(bp + 0);
    const float4 w1 = __ldg(bp + 1);
    const float4 w2 = __ldg(bp + 2);
    const float4 w3 = __ldg(bp + 3);

    const int row0 = blockIdx.y * RPC;
    const int row1 = min(row0 + RPC, total_rows);
    // first column of this warp's 128-element segment
    const int warp_col0 = blockIdx.x * (GPC * BS) + (tid & ~31) * BS;

    #pragma unroll 2
    for (int row = row0; row < row1; ++row) {
        const int s = row * row_len + warp_col0;  // logical flat start (warp)
        const int r = s & 3;                      // warp-uniform misalignment
        const float* xa = x + (s - r);            // 16B-aligned base
        float4 q = __ldcs(reinterpret_cast<const float4*>(xa) + lane);

        if (r == 0) {
            // clean path: groups coincide with aligned quads
            float4 o;
            o.x = w0.x*q.x + w0.y*q.y + w0.z*q.z + w0.w*q.w;
            o.y = w1.x*q.x + w1.y*q.y + w1.z*q.z + w1.w*q.w;
            o.z = w2.x*q.x + w2.y*q.y + w2.z*q.z + w2.w*q.w;
            o.w = w3.x*q.x + w3.y*q.y + w3.z*q.z + w3.w*q.w;
            reinterpret_cast<float4*>(y + s)[lane] = o;
        } else {
            // window: own quad + first 3 floats of next lane's quad
            float nx = __shfl_down_sync(0xffffffffu, q.x, 1);
            float ny = __shfl_down_sync(0xffffffffu, q.y, 1);
            float nz = __shfl_down_sync(0xffffffffu, q.z, 1);
            if (lane == 31) {            // patch: next 16B after warp segment
                nx = xa[128]; ny = xa[129]; nz = xa[130];
            }
            float x0, x1, x2, x3;
            if (r == 1)      { x0 = q.y; x1 = q.z; x2 = q.w; x3 = nx; }
            else if (r == 2) { x0 = q.z; x1 = q.w; x2 = nx;  x3 = ny; }
            else             { x0 = q.w; x1 = nx;  x2 = ny;  x3 = nz; }

            float y0 = w0.x*x0 + w0.y*x1 + w0.z*x2 + w0.w*x3;
            float y1 = w1.x*x0 + w1.y*x1 + w1.z*x2 + w1.w*x3;
            float y2 = w2.x*x0 + w2.y*x1 + w2.z*x2 + w2.w*x3;
            float y3 = w3.x*x0 + w3.y*x1 + w3.z*x2 + w3.w*x3;

            // reassemble aligned output quads from prev lane's tail
            float p1 = __shfl_up_sync(0xffffffffu, y1, 1);
            float p2 = __shfl_up_sync(0xffffffffu, y2, 1);
            float p3 = __shfl_up_sync(0xffffffffu, y3, 1);
            float4 o;
            if (r == 1)      { o.x = p3; o.y = y0; o.z = y1; o.w = y2; }
            else if (r == 2) { o.x = p2; o.y = p3; o.z = y0; o.w = y1; }
            else             { o.x = p1; o.y = p2; o.z = p3; o.w = y0; }

            if (lane > 0) {
                reinterpret_cast<float4*>(y + (s - r))[lane] = o;
            } else {
                // lane0's aligned quad dips into predecessor territory:
                // write only own logical elements 0..(3-r) scalar
                y[s + 0] = y0;
                if (r < 3) y[s + 1] = y1;
                if (r < 2) y[s + 2] = y2;
            }
            if (lane == 31) {
                // top r logical elements (124+k, k>=4-r) spill past last quad
                y[s + 127] = y3;
                if (r >= 2) y[s + 126] = y2;
                if (r >= 3) y[s + 125] = y1;
            }
        }
    }

    // fused remainder duty: last column-CTA handles the 3-wide diagonal tail
    if (blockIdx.x == gridDim.x - 1) {
        const int colbase = n_blocks * BS;
        const int tail = row_len - colbase;     // == rem here
        const int nrows = row1 - row0;
        const int tot = tail * nrows;
        for (int t = tid; t < tot; t += blockDim.x) {
            int rr = t / tail;
            int k  = t - rr * tail;
            int idx = (row0 + rr) * row_len + colbase + k;
            y[idx] = (k < rem) ? x[idx] * __ldg(dr + k) : 0.0f;
        }
    }
}

// Simple fallback (general shapes): thread owns a block, scalar path.
__global__ void __launch_bounds__(256) block_apply_simple_kernel(
    const float* __restrict__ x, const float* __restrict__ blocks,
    const float* __restrict__ dr, float* __restrict__ y,
    int n_blocks, int rem, int row_len, int total_rows, int rows_per_cta)
{
    const int b = blockIdx.x * blockDim.x + threadIdx.x;
    int row0 = blockIdx.y * rows_per_cta;
    int row1 = min(row0 + rows_per_cta, total_rows);
    if (b < n_blocks) {
        const float4* bp = reinterpret_cast<const float4*>(blocks) + b * BS;
        const float4 w0 = __ldg(bp+0), w1 = __ldg(bp+1),
                     w2 = __ldg(bp+2), w3 = __ldg(bp+3);
        int base = row0 * row_len + b * BS;
        for (int row = row0; row < row1; ++row, base += row_len) {
            float x0 = x[base+0], x1 = x[base+1], x2 = x[base+2], x3 = x[base+3];
            y[base+0] = w0.x*x0 + w0.y*x1 + w0.z*x2 + w0.w*x3;
            y[base+1] = w1.x*x0 + w1.y*x1 + w1.z*x2 + w1.w*x3;
            y[base+2] = w2.x*x0 + w2.y*x1 + w2.z*x2 + w2.w*x3;
            y[base+3] = w3.x*x0 + w3.y*x1 + w3.z*x2 + w3.w*x3;
        }
    } else if (b == n_blocks) {
        const int colbase = n_blocks * BS;
        const int tail = row_len - colbase;
        int base = row0 * row_len + colbase;
        for (int row = row0; row < row1; ++row, base += row_len)
            for (int t = 0; t < tail; ++t)
                y[base + t] = (t < rem) ? x[base + t] * __ldg(dr + t) : 0.0f;
    }
}

extern "C" void kernel_launch(void* const* d_in, const int* in_sizes, int n_in,
                              void* d_out, int out_size)
{
    const float* x      = (const float*)d_in[0];
    const float* blocks = (const float*)d_in[1];
    const float* dr     = (const float*)d_in[2];
    float* y = (float*)d_out;

    const int n_blocks     = in_sizes[1] / (BS * BS);   // 1024
    const int rem          = in_sizes[2];               // 3
    const int block_region = n_blocks * BS;             // 4096
    const int row_len      = block_region + rem;        // 4099
    const int total_rows   = out_size / row_len;        // 16384

    if (n_blocks % GPC == 0) {
        const int gx = n_blocks / GPC;                              // 4
        const int gy = (total_rows + RPC - 1) / RPC;                // 2048
        dim3 grid(gx, gy, 1);
        block_apply_vec_kernel<<<grid, GPC>>>(x, blocks, dr, y,
                                              n_blocks, rem, row_len, total_rows);
    } else {
        const int THREADS = 256;
        const int rows_per_cta = 8;
        dim3 grid((n_blocks + 1 + THREADS - 1) / THREADS,
                  (total_rows + rows_per_cta - 1) / rows_per_cta, 1);
        block_apply_simple_kernel<<<grid, THREADS>>>(x, blocks, dr, y,
                                                     n_blocks, rem, row_len,
                                                     total_rows, rows_per_cta);
    }
}

// round 6
// speedup vs baseline: 1.3097x; 1.3097x over previous
#include <cuda_runtime.h>
#include <cuda_bf16.h>

// y = D @ x per row, D = blockdiag(1024 x [4x4]) + diag(rem[3]).
// x: (16384, 4099) fp32. Row stride 4099 ≡ 3 (mod 4).
// Key facts exploited:
//  * With RPC=4 and row0 = 4*by, misalignment r(row i) = (3i)&3 = {0,3,2,1}
//    is COMPILE-TIME constant -> fully static specialization per row.
//  * All global traffic is aligned LDG.128/STG.128; misalignment fixed with
//    warp shuffles; lane31 patches via one aligned LDG.128 (in-bounds: last
//    patch element = buffer_end - r, r>=1).
//  * Loads for all 4 rows (+ patches) issued up-front -> MLP ~4-5/thread.

#define BS  4
#define GPC 256   // groups per CTA == blockDim.x
#define RPC 4     // rows per CTA (must be multiple of 4 for static r pattern)

struct W4 { float4 w0, w1, w2, w3; };

__device__ __forceinline__ float4 apply_w(const W4& w,
                                          float x0, float x1, float x2, float x3)
{
    float4 o;
    o.x = w.w0.x*x0 + w.w0.y*x1 + w.w0.z*x2 + w.w0.w*x3;
    o.y = w.w1.x*x0 + w.w1.y*x1 + w.w1.z*x2 + w.w1.w*x3;
    o.z = w.w2.x*x0 + w.w2.y*x1 + w.w2.z*x2 + w.w2.w*x3;
    o.w = w.w3.x*x0 + w.w3.y*x1 + w.w3.z*x2 + w.w3.w*x3;
    return o;
}

// Process one row with compile-time misalignment R (1..3).
// q     : this lane's aligned input quad (x[s-R + 4*lane .. +3])
// p     : lane31's patch quad (x[s-R+128 .. +131]), valid on lane31 only
// s     : logical flat start of the warp's 128-element segment
template<int R>
__device__ __forceinline__ void process_row_misaligned(
    float4 q, float4 p, int s, int lane, const W4& w, float* __restrict__ y)
{
    float nx = __shfl_down_sync(0xffffffffu, q.x, 1);
    float ny = __shfl_down_sync(0xffffffffu, q.y, 1);
    float nz = __shfl_down_sync(0xffffffffu, q.z, 1);
    if (lane == 31) { nx = p.x; ny = p.y; nz = p.z; }

    float x0, x1, x2, x3;
    if (R == 1)      { x0 = q.y; x1 = q.z; x2 = q.w; x3 = nx; }
    else if (R == 2) { x0 = q.z; x1 = q.w; x2 = nx;  x3 = ny; }
    else             { x0 = q.w; x1 = nx;  x2 = ny;  x3 = nz; }

    float4 v = apply_w(w, x0, x1, x2, x3);

    // reassemble aligned output quads from previous lane's tail
    float p1 = __shfl_up_sync(0xffffffffu, v.y, 1);
    float p2 = __shfl_up_sync(0xffffffffu, v.z, 1);
    float p3 = __shfl_up_sync(0xffffffffu, v.w, 1);
    float4 o;
    if (R == 1)      { o.x = p3; o.y = v.x; o.z = v.y; o.w = v.z; }
    else if (R == 2) { o.x = p2; o.y = p3; o.z = v.x; o.w = v.y; }
    else             { o.x = p1; o.y = p2; o.z = p3; o.w = v.x; }

    if (lane > 0) {
        reinterpret_cast<float4*>(y + (s - R))[lane] = o;
    } else {
        y[s + 0] = v.x;
        if (R < 3) y[s + 1] = v.y;
        if (R < 2) y[s + 2] = v.z;
    }
    if (lane == 31) {
        y[s + 127] = v.w;
        if (R >= 2) y[s + 126] = v.z;
        if (R >= 3) y[s + 125] = v.y;
    }
}

__global__ void __launch_bounds__(256, 4) block_apply_vec4_kernel(
    const float* __restrict__ x,
    const float* __restrict__ blocks,
    const float* __restrict__ dr,
    float* __restrict__ y,
    int n_blocks, int rem, int row_len, int total_rows)
{
    const int tid  = threadIdx.x;
    const int lane = tid & 31;
    const int g    = blockIdx.x * GPC + tid;

    W4 w;
    {
        const float4* bp = reinterpret_cast<const float4*>(blocks) + g * BS;
        w.w0 = __ldg(bp + 0); w.w1 = __ldg(bp + 1);
        w.w2 = __ldg(bp + 2); w.w3 = __ldg(bp + 3);
    }

    const int row0 = blockIdx.y * RPC;                    // multiple of 4
    const int warp_col0 = blockIdx.x * (GPC * BS) + (tid & ~31) * BS;
    const int s0 = row0 * row_len + warp_col0;            // s0 & 3 == 0

    if (row0 + RPC <= total_rows) {
        // r pattern for rows 0..3: {0,3,2,1} (static)
        const float4* a0 = reinterpret_cast<const float4*>(x + s0);
        const float4* a1 = reinterpret_cast<const float4*>(x + s0 +     row_len - 3);
        const float4* a2 = reinterpret_cast<const float4*>(x + s0 + 2 * row_len - 2);
        const float4* a3 = reinterpret_cast<const float4*>(x + s0 + 3 * row_len - 1);

        // ---- load phase: everything in flight before compute ----
        float4 q0 = __ldcs(a0 + lane);
        float4 q1 = __ldcs(a1 + lane);
        float4 q2 = __ldcs(a2 + lane);
        float4 q3 = __ldcs(a3 + lane);
        float4 p1, p2, p3;
        if (lane == 31) {
            p1 = __ldcs(a1 + 32);
            p2 = __ldcs(a2 + 32);
            p3 = __ldcs(a3 + 32);
        }

        // ---- compute/store phase ----
        {   // row 0, r = 0: clean path
            float4 o = apply_w(w, q0.x, q0.y, q0.z, q0.w);
            reinterpret_cast<float4*>(y + s0)[lane] = o;
        }
        process_row_misaligned<3>(q1, p1, s0 +     row_len, lane, w, y);
        process_row_misaligned<2>(q2, p2, s0 + 2 * row_len, lane, w, y);
        process_row_misaligned<1>(q3, p3, s0 + 3 * row_len, lane, w, y);
    } else {
        // generic tail rows: scalar per-group path
        for (int row = row0; row < total_rows; ++row) {
            int base = row * row_len + g * BS;
            float x0 = x[base+0], x1 = x[base+1], x2 = x[base+2], x3 = x[base+3];
            float4 o = apply_w(w, x0, x1, x2, x3);
            y[base+0] = o.x; y[base+1] = o.y; y[base+2] = o.z; y[base+3] = o.w;
        }
    }

    // fused remainder duty: last column-CTA handles the diagonal tail
    if (blockIdx.x == gridDim.x - 1) {
        const int colbase = n_blocks * BS;
        const int tail = row_len - colbase;                 // == rem here
        const int row1 = min(row0 + RPC, total_rows);
        const int nrows = row1 - row0;
        const int tot = tail * nrows;
        for (int t = tid; t < tot; t += blockDim.x) {
            int rr = t / tail;
            int k  = t - rr * tail;
            int idx = (row0 + rr) * row_len + colbase + k;
            y[idx] = (k < rem) ? x[idx] * __ldg(dr + k) : 0.0f;
        }
    }
}

// Fallback for general shapes: thread owns a block, scalar path.
__global__ void __launch_bounds__(256) block_apply_simple_kernel(
    const float* __restrict__ x, const float* __restrict__ blocks,
    const float* __restrict__ dr, float* __restrict__ y,
    int n_blocks, int rem, int row_len, int total_rows, int rows_per_cta)
{
    const int b = blockIdx.x * blockDim.x + threadIdx.x;
    int row0 = blockIdx.y * rows_per_cta;
    int row1 = min(row0 + rows_per_cta, total_rows);
    if (b < n_blocks) {
        const float4* bp = reinterpret_cast<const float4*>(blocks) + b * BS;
        W4 w; w.w0 = __ldg(bp+0); w.w1 = __ldg(bp+1);
              w.w2 = __ldg(bp+2); w.w3 = __ldg(bp+3);
        int base = row0 * row_len + b * BS;
        for (int row = row0; row < row1; ++row, base += row_len) {
            float4 o = apply_w(w, x[base+0], x[base+1], x[base+2], x[base+3]);
            y[base+0] = o.x; y[base+1] = o.y; y[base+2] = o.z; y[base+3] = o.w;
        }
    } else if (b == n_blocks) {
        const int colbase = n_blocks * BS;
        const int tail = row_len - colbase;
        int base = row0 * row_len + colbase;
        for (int row = row0; row < row1; ++row, base += row_len)
            for (int t = 0; t < tail; ++t)
                y[base + t] = (t < rem) ? x[base + t] * __ldg(dr + t) : 0.0f;
    }
}

extern "C" void kernel_launch(void* const* d_in, const int* in_sizes, int n_in,
                              void* d_out, int out_size)
{
    const float* x      = (const float*)d_in[0];
    const float* blocks = (const float*)d_in[1];
    const float* dr     = (const float*)d_in[2];
    float* y = (float*)d_out;

    const int n_blocks     = in_sizes[1] / (BS * BS);   // 1024
    const int rem          = in_sizes[2];               // 3
    const int block_region = n_blocks * BS;             // 4096
    const int row_len      = block_region + rem;        // 4099
    const int total_rows   = out_size / row_len;        // 16384

    if (n_blocks % GPC == 0 && (row_len & 3) != 0) {
        const int gx = n_blocks / GPC;                              // 4
        const int gy = (total_rows + RPC - 1) / RPC;                // 4096
        dim3 grid(gx, gy, 1);
        block_apply_vec4_kernel<<<grid, GPC>>>(x, blocks, dr, y,
                                               n_blocks, rem, row_len, total_rows);
    } else {
        const int THREADS = 256;
        const int rows_per_cta = 8;
        dim3 grid((n_blocks + 1 + THREADS - 1) / THREADS,
                  (total_rows + rows_per_cta - 1) / rows_per_cta, 1);
        block_apply_simple_kernel<<<grid, THREADS>>>(x, blocks, dr, y,
                                                     n_blocks, rem, row_len,
                                                     total_rows, rows_per_cta);
    }
}